// round 1
// baseline (speedup 1.0000x reference)
#include <cuda_runtime.h>
#include <math.h>
#include <stdint.h>

#define B_ 2
#define S_ 1024
#define E_ 1024
#define D_ 2048
#define H_ 8
#define KV_ 4
#define HD_ 256
#define WINDOW_ 512
#define SOFTCAP_ 50.0f
#define SCALE_ 0.0625f   /* 256^-0.5 */

// ---------------- scratch (device globals: allocation-free) ----------------
__device__ float g_q     [B_*S_*H_ *HD_];   // [B*S, H, HD]
__device__ float g_kself [B_*S_*KV_*HD_];   // [B*S, KV, HD]
__device__ float g_vself [B_*S_*KV_*HD_];
__device__ float g_kcross[B_*E_*KV_*HD_];
__device__ float g_vcross[B_*E_*KV_*HD_];
__device__ float g_attn  [B_*S_*H_ *HD_];   // [B*S, H, HD]
__device__ int   g_seg   [B_*S_];

// ---------------- SGEMM: C[M,N] = A[M,K] @ B[K,N], all row-major -----------
// BM=BN=128, BK=8, 256 threads, 8x8 per thread. All dims divisible.
__global__ __launch_bounds__(256) void sgemm_kernel(
    int M, int N, int K,
    const float* __restrict__ A, const float* __restrict__ B, float* __restrict__ C)
{
    const int BM = 128, BN = 128, BK = 8;
    __shared__ float As[BK][BM];
    __shared__ float Bs[BK][BN];
    int tid = threadIdx.x;
    int bx = blockIdx.x, by = blockIdx.y;
    int trow = tid >> 4;          // 0..15
    int tcol = tid & 15;          // 0..15

    const float* Ab = A + (size_t)by * BM * K;
    const float* Bb = B + (size_t)bx * BN;
    float*       Cb = C + (size_t)by * BM * N + (size_t)bx * BN;

    int aRow = tid >> 1;          // 0..127
    int aCol = (tid & 1) << 2;    // 0 or 4
    int bRow = tid >> 5;          // 0..7
    int bCol = (tid & 31) << 2;   // 0..124

    float acc[8][8];
    #pragma unroll
    for (int i = 0; i < 8; i++)
        #pragma unroll
        for (int j = 0; j < 8; j++) acc[i][j] = 0.f;

    for (int k0 = 0; k0 < K; k0 += BK) {
        float4 av = *reinterpret_cast<const float4*>(Ab + (size_t)aRow * K + k0 + aCol);
        As[aCol+0][aRow] = av.x;
        As[aCol+1][aRow] = av.y;
        As[aCol+2][aRow] = av.z;
        As[aCol+3][aRow] = av.w;
        *reinterpret_cast<float4*>(&Bs[bRow][bCol]) =
            *reinterpret_cast<const float4*>(Bb + (size_t)(k0 + bRow) * N + bCol);
        __syncthreads();
        #pragma unroll
        for (int k = 0; k < BK; k++) {
            float4 a0 = *reinterpret_cast<float4*>(&As[k][trow*8]);
            float4 a1 = *reinterpret_cast<float4*>(&As[k][trow*8+4]);
            float4 b0 = *reinterpret_cast<float4*>(&Bs[k][tcol*8]);
            float4 b1 = *reinterpret_cast<float4*>(&Bs[k][tcol*8+4]);
            float ra[8] = {a0.x,a0.y,a0.z,a0.w,a1.x,a1.y,a1.z,a1.w};
            float rb[8] = {b0.x,b0.y,b0.z,b0.w,b1.x,b1.y,b1.z,b1.w};
            #pragma unroll
            for (int i = 0; i < 8; i++)
                #pragma unroll
                for (int j = 0; j < 8; j++)
                    acc[i][j] += ra[i] * rb[j];
        }
        __syncthreads();
    }
    #pragma unroll
    for (int i = 0; i < 8; i++) {
        #pragma unroll
        for (int j = 0; j < 8; j += 4) {
            float4 v = make_float4(acc[i][j], acc[i][j+1], acc[i][j+2], acc[i][j+3]);
            *reinterpret_cast<float4*>(Cb + (size_t)(trow*8+i) * N + tcol*8+j) = v;
        }
    }
}

// ---------------- segment ids (cumsum of position resets) ------------------
__global__ void seg_kernel(const int* __restrict__ pos) {
    int b = threadIdx.x;
    if (b >= B_) return;
    int s = 0, prev = 0;
    for (int i = 0; i < S_; i++) {
        int p = pos[b*S_ + i];
        if (i == 0 || p <= prev) s++;
        prev = p;
        g_seg[b*S_ + i] = s;
    }
}

// ---------------- fused RMS norm (+ optional RoPE), in place ----------------
// buf: [B*T, nheads, HD]; one block (256 thr) per (token, head)
__global__ __launch_bounds__(256) void norm_rope_kernel(
    float* __restrict__ buf, const float* __restrict__ nw,
    const float* __restrict__ cs, const float* __restrict__ sn,
    int nheads, int do_rope)
{
    int blk = blockIdx.x;
    int h = blk % nheads;
    int t = blk / nheads;
    float* x = buf + ((size_t)t * nheads + h) * HD_;
    int d = threadIdx.x;
    float v = x[d];
    float ss = v * v;
    __shared__ float red[8];
    #pragma unroll
    for (int o = 16; o; o >>= 1) ss += __shfl_xor_sync(0xffffffffu, ss, o);
    if ((d & 31) == 0) red[d >> 5] = ss;
    __syncthreads();
    float tot = 0.f;
    #pragma unroll
    for (int i = 0; i < 8; i++) tot += red[i];
    float inv = rsqrtf(tot * (1.0f / HD_) + 1e-6f);
    float xn = v * inv * (1.0f + nw[d]);
    if (do_rope) {
        __shared__ float sx[HD_];
        sx[d] = xn;
        __syncthreads();
        float rot = (d < HD_/2) ? -sx[d + HD_/2] : sx[d - HD_/2];
        xn = xn * cs[(size_t)t * HD_ + d] + rot * sn[(size_t)t * HD_ + d];
    }
    x[d] = xn;
}

// ---------------- attention: flash-style, 32 q/block, 32-key tiles ----------
// 256 threads = 8 warps, 4 queries per warp. dim d owned by lane l at e*32+l.
__global__ __launch_bounds__(256) void attn_kernel(
    const int* __restrict__ dmask, const int* __restrict__ emask)
{
    extern __shared__ float smem[];
    float (*Ks)[HD_] = (float(*)[HD_])smem;
    float (*Vs)[HD_] = (float(*)[HD_])(smem + 32 * HD_);

    int b = blockIdx.z, h = blockIdx.y, qt = blockIdx.x;
    int kv = h >> 1;                      // rep = H/KV = 2
    int tid = threadIdx.x;
    int lane = tid & 31, w = tid >> 5;
    int qbase = qt * 32;
    int q0 = qbase + w * 4;

    float qf[4][8], o[4][8];
    float m[4], l[4];
    int myseg[4];
    #pragma unroll
    for (int qi = 0; qi < 4; qi++) {
        const float* qp = g_q + ((size_t)((b*S_ + q0 + qi)*H_ + h)) * HD_;
        #pragma unroll
        for (int e = 0; e < 8; e++) { qf[qi][e] = qp[e*32 + lane]; o[qi][e] = 0.f; }
        m[qi] = -3.0e38f; l[qi] = 0.f;
        myseg[qi] = g_seg[b*S_ + q0 + qi];
    }

    // self tiles needed: sliding window of 512 behind, causal ahead
    int lo = qbase - (WINDOW_ - 1);
    int t_lo = (lo <= 0) ? 0 : (lo >> 5);
    int nself = qt - t_lo + 1;
    int npass = nself + E_ / 32;

    for (int pass = 0; pass < npass; pass++) {
        bool is_self = pass < nself;
        int jg0, jloc0;
        const float *kb, *vb;
        if (is_self) { jg0 = (t_lo + pass) * 32; jloc0 = jg0; kb = g_kself; vb = g_vself; }
        else { int t = pass - nself; jg0 = S_ + t*32; jloc0 = t*32; kb = g_kcross; vb = g_vcross; }

        __syncthreads();
        #pragma unroll
        for (int r = 0; r < 8; r++) {
            int i = tid + 256 * r;
            int row = i >> 6;
            int c4 = (i & 63) << 2;
            size_t off = ((size_t)((b*1024 + jloc0 + row)*KV_ + kv)) * HD_ + c4;
            *(float4*)&Ks[row][c4] = *(const float4*)(kb + off);
            *(float4*)&Vs[row][c4] = *(const float4*)(vb + off);
        }
        __syncthreads();

        // per-lane key metadata (key index jg0+lane)
        int jg = jg0 + lane;
        bool keyvalid; int segj = 0;
        if (is_self) {
            keyvalid = dmask[b*S_ + jg] != 0;
            segj = g_seg[b*S_ + jg];
        } else {
            keyvalid = emask[b*E_ + (jg - S_)] != 0;
        }

        // scores: lane j ends up holding raw dot for key jg0+j
        float sraw[4];
        #pragma unroll
        for (int j = 0; j < 32; j++) {
            float kf[8];
            #pragma unroll
            for (int e = 0; e < 8; e++) kf[e] = Ks[j][e*32 + lane];
            #pragma unroll
            for (int qi = 0; qi < 4; qi++) {
                float d = 0.f;
                #pragma unroll
                for (int e = 0; e < 8; e++) d += qf[qi][e] * kf[e];
                #pragma unroll
                for (int off = 16; off; off >>= 1) d += __shfl_xor_sync(0xffffffffu, d, off);
                if (lane == j) sraw[qi] = d;
            }
        }

        float p[4];
        #pragma unroll
        for (int qi = 0; qi < 4; qi++) {
            int q = q0 + qi;
            float sc = sraw[qi] * SCALE_;
            sc = SOFTCAP_ * tanhf(sc * (1.0f / SOFTCAP_));
            bool valid = keyvalid;
            if (is_self) valid = valid && (jg <= q) && (q - jg < WINDOW_) && (segj == myseg[qi]);
            if (!valid) sc = -1e30f;
            float tm = sc;
            #pragma unroll
            for (int off = 16; off; off >>= 1) tm = fmaxf(tm, __shfl_xor_sync(0xffffffffu, tm, off));
            float mnew = fmaxf(m[qi], tm);
            float corr = __expf(m[qi] - mnew);
            m[qi] = mnew;
            float pp = __expf(sc - mnew);
            p[qi] = pp;
            float ps = pp;
            #pragma unroll
            for (int off = 16; off; off >>= 1) ps += __shfl_xor_sync(0xffffffffu, ps, off);
            l[qi] = l[qi] * corr + ps;
            #pragma unroll
            for (int e = 0; e < 8; e++) o[qi][e] *= corr;
        }

        #pragma unroll
        for (int j = 0; j < 32; j++) {
            float pj0 = __shfl_sync(0xffffffffu, p[0], j);
            float pj1 = __shfl_sync(0xffffffffu, p[1], j);
            float pj2 = __shfl_sync(0xffffffffu, p[2], j);
            float pj3 = __shfl_sync(0xffffffffu, p[3], j);
            #pragma unroll
            for (int e = 0; e < 8; e++) {
                float v = Vs[j][e*32 + lane];
                o[0][e] += pj0 * v;
                o[1][e] += pj1 * v;
                o[2][e] += pj2 * v;
                o[3][e] += pj3 * v;
            }
        }
    }

    #pragma unroll
    for (int qi = 0; qi < 4; qi++) {
        float inv = 1.0f / l[qi];
        float* op = g_attn + ((size_t)((b*S_ + q0 + qi)*H_ + h)) * HD_;
        #pragma unroll
        for (int e = 0; e < 8; e++) op[e*32 + lane] = o[qi][e] * inv;
    }
}

// ---------------- launch ----------------------------------------------------
extern "C" void kernel_launch(void* const* d_in, const int* in_sizes, int n_in,
                              void* d_out, int out_size)
{
    const float* hs   = (const float*)d_in[0];
    const float* enc  = (const float*)d_in[1];
    const float* cosp = (const float*)d_in[2];
    const float* sinp = (const float*)d_in[3];
    const float* wq   = (const float*)d_in[4];
    const float* wk   = (const float*)d_in[5];
    const float* wv   = (const float*)d_in[6];
    const float* wo   = (const float*)d_in[7];
    const float* qnw  = (const float*)d_in[8];
    const float* knw  = (const float*)d_in[9];
    const int*   dmsk = (const int*)d_in[10];
    const int*   emsk = (const int*)d_in[11];
    const int*   pos  = (const int*)d_in[12];
    float* out = (float*)d_out;

    float *gq, *gks, *gvs, *gkc, *gvc, *gat;
    cudaGetSymbolAddress((void**)&gq,  g_q);
    cudaGetSymbolAddress((void**)&gks, g_kself);
    cudaGetSymbolAddress((void**)&gvs, g_vself);
    cudaGetSymbolAddress((void**)&gkc, g_kcross);
    cudaGetSymbolAddress((void**)&gvc, g_vcross);
    cudaGetSymbolAddress((void**)&gat, g_attn);

    // projections
    sgemm_kernel<<<dim3((H_*HD_)/128, (B_*S_)/128), 256>>>(B_*S_, H_*HD_, D_, hs,  wq, gq);
    sgemm_kernel<<<dim3((KV_*HD_)/128,(B_*S_)/128), 256>>>(B_*S_, KV_*HD_, D_, hs,  wk, gks);
    sgemm_kernel<<<dim3((KV_*HD_)/128,(B_*S_)/128), 256>>>(B_*S_, KV_*HD_, D_, hs,  wv, gvs);
    sgemm_kernel<<<dim3((KV_*HD_)/128,(B_*E_)/128), 256>>>(B_*E_, KV_*HD_, D_, enc, wk, gkc);
    sgemm_kernel<<<dim3((KV_*HD_)/128,(B_*E_)/128), 256>>>(B_*E_, KV_*HD_, D_, enc, wv, gvc);

    // segments, norms, rope
    seg_kernel<<<1, 32>>>(pos);
    norm_rope_kernel<<<B_*S_*H_,  256>>>(gq,  qnw, cosp, sinp, H_,  1);
    norm_rope_kernel<<<B_*S_*KV_, 256>>>(gks, knw, cosp, sinp, KV_, 1);
    norm_rope_kernel<<<B_*E_*KV_, 256>>>(gkc, knw, cosp, sinp, KV_, 0);

    // attention (64 KB dynamic smem)
    int smem_bytes = 32 * HD_ * 2 * (int)sizeof(float);
    cudaFuncSetAttribute(attn_kernel, cudaFuncAttributeMaxDynamicSharedMemorySize, smem_bytes);
    attn_kernel<<<dim3(S_/32, H_, B_), 256, smem_bytes>>>(dmsk, emsk);

    // output projection
    sgemm_kernel<<<dim3(D_/128, (B_*S_)/128), 256>>>(B_*S_, D_, H_*HD_, gat, wo, out);
}

// round 3
// speedup vs baseline: 1.6752x; 1.6752x over previous
#include <cuda_runtime.h>
#include <cuda_bf16.h>
#include <math.h>
#include <stdint.h>

#define B_ 2
#define S_ 1024
#define E_ 1024
#define D_ 2048
#define H_ 8
#define KV_ 4
#define HD_ 256
#define WINDOW_ 512
#define SOFTCAP_ 50.0f
#define SCALE_ 0.0625f   /* 256^-0.5 */

// ---------------- scratch (device globals: allocation-free) ----------------
__device__ float g_q     [B_*S_*H_ *HD_];   // [B*S, H, HD]
__device__ float g_kself [B_*S_*KV_*HD_];
__device__ float g_vself [B_*S_*KV_*HD_];
__device__ float g_kcross[B_*E_*KV_*HD_];
__device__ float g_vcross[B_*E_*KV_*HD_];
__device__ float g_attn  [B_*S_*H_ *HD_];
__device__ int   g_seg   [B_*S_];
// bf16 split buffers (activations [M,K] row-major, weights transposed [N,K])
__device__ __nv_bfloat16 g_act_hi[2048*2048];
__device__ __nv_bfloat16 g_act_lo[2048*2048];
__device__ __nv_bfloat16 g_wt_hi [2048*2048];
__device__ __nv_bfloat16 g_wt_lo [2048*2048];

// ================== PTX helpers (baseline-ISA only, no tcgen05) ============
__device__ __forceinline__ uint32_t smem_u32(const void* p){
    uint32_t a;
    asm("{ .reg .u64 t; cvta.to.shared.u64 t, %1; cvt.u32.u64 %0, t; }" : "=r"(a) : "l"(p));
    return a;
}
__device__ __forceinline__ void cpa16(uint32_t s, const void* g){
    asm volatile("cp.async.cg.shared.global [%0], [%1], 16;" :: "r"(s), "l"(g) : "memory");
}
__device__ __forceinline__ void cp_commit(){
    asm volatile("cp.async.commit_group;" ::: "memory");
}
template<int N> __device__ __forceinline__ void cp_wait(){
    asm volatile("cp.async.wait_group %0;" :: "n"(N) : "memory");
}
#define MMA16816(d, a, b) \
    asm volatile("mma.sync.aligned.m16n8k16.row.col.f32.bf16.bf16.f32 " \
        "{%0,%1,%2,%3},{%4,%5,%6,%7},{%8,%9},{%0,%1,%2,%3};" \
        : "+f"((d)[0]), "+f"((d)[1]), "+f"((d)[2]), "+f"((d)[3]) \
        : "r"((a)[0]), "r"((a)[1]), "r"((a)[2]), "r"((a)[3]), \
          "r"((b)[0]), "r"((b)[1]))

// ================== HMMA bf16x3 GEMM ==================
// C[M,N] = A[M,K] @ Bt[N,K]^T ; A,Bt as bf16 hi/lo splits, K-contiguous.
// BM=BN=128, BK=32, 4-stage cp.async pipeline, 256 threads (8 warps, 4x2).
// smem rows padded to 80B (stride 20 words): conflict-free fragment loads.
#define LDROW 80
#define BUFB (128*LDROW)         /* 10240 B: one of {Ah,Al,Bh,Bl} */
#define STG_BYTES (4*BUFB)       /* 40960 B per stage */
#define GEMM_SMEM (4*STG_BYTES)  /* 163840 B */

__global__ __launch_bounds__(256) void gemm_hmma_kernel(
    int M, int N, int K,
    const __nv_bfloat16* __restrict__ Ahi, const __nv_bfloat16* __restrict__ Alo,
    const __nv_bfloat16* __restrict__ Bhi, const __nv_bfloat16* __restrict__ Blo,
    float* __restrict__ C)
{
    extern __shared__ char dsm[];
    const uint32_t sb = smem_u32(dsm);
    const int tid = threadIdx.x;
    const int lane = tid & 31, w = tid >> 5;
    const int g = lane >> 2, tg = lane & 3;
    const int wm = w & 3, wn = w >> 2;
    const int bx = blockIdx.x, by = blockIdx.y;

    const __nv_bfloat16* gp0 = Ahi + (size_t)by * 128 * K;
    const __nv_bfloat16* gp1 = Alo + (size_t)by * 128 * K;
    const __nv_bfloat16* gp2 = Bhi + (size_t)bx * 128 * K;
    const __nv_bfloat16* gp3 = Blo + (size_t)bx * 128 * K;

    float acc[2][8][4];
    #pragma unroll
    for (int mt = 0; mt < 2; mt++)
        #pragma unroll
        for (int nt = 0; nt < 8; nt++)
            #pragma unroll
            for (int i = 0; i < 4; i++) acc[mt][nt][i] = 0.f;

    const int niter = K >> 5;   // BK=32

    // stage loader: 2048 16B-chunks, 8 per thread, coalesced (c = i*256+tid)
    auto load_stage = [&](int stage, int k0){
        #pragma unroll
        for (int i = 0; i < 8; i++){
            int c = i * 256 + tid;
            int r = (c >> 2) & 127;
            int ch = c & 3;
            uint32_t saddr = sb + stage * STG_BYTES + (c >> 9) * BUFB
                           + r * LDROW + ch * 16;
            const __nv_bfloat16* gp = (i < 2) ? gp0 : (i < 4) ? gp1 : (i < 6) ? gp2 : gp3;
            cpa16(saddr, gp + (size_t)r * K + k0 + ch * 8);
        }
        cp_commit();
    };

    load_stage(0, 0);
    load_stage(1, 32);
    load_stage(2, 64);

    for (int it = 0; it < niter; it++){
        cp_wait<2>();
        __syncthreads();
        if (it + 3 < niter) load_stage((it + 3) & 3, (it + 3) * 32);

        const char* st = dsm + (it & 3) * STG_BYTES;
        #pragma unroll
        for (int ks = 0; ks < 32; ks += 16){
            const int acolB = (ks + 2 * tg) * 2;     // byte offset of half col
            uint32_t ah[2][4], al[2][4];
            #pragma unroll
            for (int mt = 0; mt < 2; mt++){
                const char* p = st + (wm * 32 + mt * 16 + g) * LDROW + acolB;
                ah[mt][0] = *(const uint32_t*)(p);
                ah[mt][2] = *(const uint32_t*)(p + 16);
                ah[mt][1] = *(const uint32_t*)(p + 8 * LDROW);
                ah[mt][3] = *(const uint32_t*)(p + 8 * LDROW + 16);
                const char* q = p + BUFB;
                al[mt][0] = *(const uint32_t*)(q);
                al[mt][2] = *(const uint32_t*)(q + 16);
                al[mt][1] = *(const uint32_t*)(q + 8 * LDROW);
                al[mt][3] = *(const uint32_t*)(q + 8 * LDROW + 16);
            }
            uint32_t bh[8][2], bl[8][2];
            #pragma unroll
            for (int nt = 0; nt < 8; nt++){
                const char* p = st + 2 * BUFB + (wn * 64 + nt * 8 + g) * LDROW + acolB;
                bh[nt][0] = *(const uint32_t*)(p);
                bh[nt][1] = *(const uint32_t*)(p + 16);
                const char* q = p + BUFB;
                bl[nt][0] = *(const uint32_t*)(q);
                bl[nt][1] = *(const uint32_t*)(q + 16);
            }
            #pragma unroll
            for (int mt = 0; mt < 2; mt++)
                #pragma unroll
                for (int nt = 0; nt < 8; nt++){
                    MMA16816(acc[mt][nt], ah[mt], bh[nt]);
                    MMA16816(acc[mt][nt], ah[mt], bl[nt]);
                    MMA16816(acc[mt][nt], al[mt], bh[nt]);
                }
        }
    }

    // epilogue
    #pragma unroll
    for (int mt = 0; mt < 2; mt++){
        int r = by * 128 + wm * 32 + mt * 16 + g;
        #pragma unroll
        for (int nt = 0; nt < 8; nt++){
            int c = bx * 128 + wn * 64 + nt * 8 + 2 * tg;
            *(float2*)(C + (size_t)r * N + c)       = make_float2(acc[mt][nt][0], acc[mt][nt][1]);
            *(float2*)(C + (size_t)(r + 8) * N + c) = make_float2(acc[mt][nt][2], acc[mt][nt][3]);
        }
    }
}

// ---------------- fp32 -> bf16 hi/lo split (elementwise) -------------------
__global__ __launch_bounds__(256) void asplit_kernel(
    const float* __restrict__ x, __nv_bfloat16* __restrict__ hi,
    __nv_bfloat16* __restrict__ lo, int n)
{
    int i = (blockIdx.x * 256 + threadIdx.x) * 4;
    if (i >= n) return;
    float4 v = *(const float4*)(x + i);
    float a[4] = {v.x, v.y, v.z, v.w};
    __nv_bfloat16 h[4], l[4];
    #pragma unroll
    for (int j = 0; j < 4; j++){
        h[j] = __float2bfloat16(a[j]);
        l[j] = __float2bfloat16(a[j] - __bfloat162float(h[j]));
    }
    *(__nv_bfloat162*)(hi + i)     = __nv_bfloat162(h[0], h[1]);
    *(__nv_bfloat162*)(hi + i + 2) = __nv_bfloat162(h[2], h[3]);
    *(__nv_bfloat162*)(lo + i)     = __nv_bfloat162(l[0], l[1]);
    *(__nv_bfloat162*)(lo + i + 2) = __nv_bfloat162(l[2], l[3]);
}

// ---------------- weight transpose + split: W[K,N] -> Wt[N,K] bf16 ---------
__global__ __launch_bounds__(256) void wsplit_kernel(
    const float* __restrict__ W, __nv_bfloat16* __restrict__ hi,
    __nv_bfloat16* __restrict__ lo, int K, int N)
{
    __shared__ float t[32][33];
    int n0 = blockIdx.x * 32, k0 = blockIdx.y * 32;
    int tx = threadIdx.x & 31, ty = threadIdx.x >> 5;
    #pragma unroll
    for (int r = 0; r < 32; r += 8)
        t[ty + r][tx] = W[(size_t)(k0 + ty + r) * N + n0 + tx];
    __syncthreads();
    #pragma unroll
    for (int r = 0; r < 32; r += 8){
        float v = t[tx][ty + r];
        __nv_bfloat16 h = __float2bfloat16(v);
        __nv_bfloat16 l = __float2bfloat16(v - __bfloat162float(h));
        size_t o = (size_t)(n0 + ty + r) * K + k0 + tx;
        hi[o] = h; lo[o] = l;
    }
}

// ---------------- segment ids: parallel Hillis-Steele scan ------------------
__global__ __launch_bounds__(1024) void seg_kernel(const int* __restrict__ pos) {
    __shared__ int sh[1024];
    int b = blockIdx.x, i = threadIdx.x;
    int p = pos[b*S_ + i];
    int flag = (i == 0) ? 1 : ((p <= pos[b*S_ + i - 1]) ? 1 : 0);
    sh[i] = flag;
    __syncthreads();
    #pragma unroll
    for (int off = 1; off < 1024; off <<= 1){
        int v = sh[i];
        int add = (i >= off) ? sh[i - off] : 0;
        __syncthreads();
        sh[i] = v + add;
        __syncthreads();
    }
    g_seg[b*S_ + i] = sh[i];
}

// ---------------- fused RMS norm (+ optional RoPE), in place ----------------
__global__ __launch_bounds__(256) void norm_rope_kernel(
    float* __restrict__ buf, const float* __restrict__ nw,
    const float* __restrict__ cs, const float* __restrict__ sn,
    int nheads, int do_rope)
{
    int blk = blockIdx.x;
    int h = blk % nheads;
    int t = blk / nheads;
    float* x = buf + ((size_t)t * nheads + h) * HD_;
    int d = threadIdx.x;
    float v = x[d];
    float ss = v * v;
    __shared__ float red[8];
    #pragma unroll
    for (int o = 16; o; o >>= 1) ss += __shfl_xor_sync(0xffffffffu, ss, o);
    if ((d & 31) == 0) red[d >> 5] = ss;
    __syncthreads();
    float tot = 0.f;
    #pragma unroll
    for (int i = 0; i < 8; i++) tot += red[i];
    float inv = rsqrtf(tot * (1.0f / HD_) + 1e-6f);
    float xn = v * inv * (1.0f + nw[d]);
    if (do_rope) {
        __shared__ float sx[HD_];
        sx[d] = xn;
        __syncthreads();
        float rot = (d < HD_/2) ? -sx[d + HD_/2] : sx[d - HD_/2];
        xn = xn * cs[(size_t)t * HD_ + d] + rot * sn[(size_t)t * HD_ + d];
    }
    x[d] = xn;
}

// ---------------- attention: flash-style, 32 q/block, 32-key tiles ----------
__device__ __forceinline__ float softcap_tanh(float sc){
    // SOFTCAP * tanh(sc/SOFTCAP) via exp identity (fast, ~1e-7 accurate)
    float x2 = fabsf(sc) * (2.0f / SOFTCAP_);
    float e = __expf(-x2);
    float t = __fdividef(1.0f - e, 1.0f + e);
    return copysignf(SOFTCAP_ * t, sc);
}

__global__ __launch_bounds__(256) void attn_kernel(
    const int* __restrict__ dmask, const int* __restrict__ emask)
{
    extern __shared__ float smem[];
    float (*Ks)[HD_] = (float(*)[HD_])smem;
    float (*Vs)[HD_] = (float(*)[HD_])(smem + 32 * HD_);

    int b = blockIdx.z, h = blockIdx.y, qt = blockIdx.x;
    int kv = h >> 1;
    int tid = threadIdx.x;
    int lane = tid & 31, w = tid >> 5;
    int qbase = qt * 32;
    int q0 = qbase + w * 4;

    float qf[4][8], o[4][8];
    float m[4], l[4];
    int myseg[4];
    #pragma unroll
    for (int qi = 0; qi < 4; qi++) {
        const float* qp = g_q + ((size_t)((b*S_ + q0 + qi)*H_ + h)) * HD_;
        #pragma unroll
        for (int e = 0; e < 8; e++) { qf[qi][e] = qp[e*32 + lane]; o[qi][e] = 0.f; }
        m[qi] = -3.0e38f; l[qi] = 0.f;
        myseg[qi] = g_seg[b*S_ + q0 + qi];
    }

    int lo = qbase - (WINDOW_ - 1);
    int t_lo = (lo <= 0) ? 0 : (lo >> 5);
    int nself = qt - t_lo + 1;
    int npass = nself + E_ / 32;

    for (int pass = 0; pass < npass; pass++) {
        bool is_self = pass < nself;
        int jg0, jloc0;
        const float *kb, *vb;
        if (is_self) { jg0 = (t_lo + pass) * 32; jloc0 = jg0; kb = g_kself; vb = g_vself; }
        else { int t = pass - nself; jg0 = S_ + t*32; jloc0 = t*32; kb = g_kcross; vb = g_vcross; }

        __syncthreads();
        #pragma unroll
        for (int r = 0; r < 8; r++) {
            int i = tid + 256 * r;
            int row = i >> 6;
            int c4 = (i & 63) << 2;
            size_t off = ((size_t)((b*1024 + jloc0 + row)*KV_ + kv)) * HD_ + c4;
            *(float4*)&Ks[row][c4] = *(const float4*)(kb + off);
            *(float4*)&Vs[row][c4] = *(const float4*)(vb + off);
        }
        __syncthreads();

        int jg = jg0 + lane;
        bool keyvalid; int segj = 0;
        if (is_self) {
            keyvalid = dmask[b*S_ + jg] != 0;
            segj = g_seg[b*S_ + jg];
        } else {
            keyvalid = emask[b*E_ + (jg - S_)] != 0;
        }

        float sraw[4];
        #pragma unroll
        for (int j = 0; j < 32; j++) {
            float kf[8];
            #pragma unroll
            for (int e = 0; e < 8; e++) kf[e] = Ks[j][e*32 + lane];
            #pragma unroll
            for (int qi = 0; qi < 4; qi++) {
                float d = 0.f;
                #pragma unroll
                for (int e = 0; e < 8; e++) d += qf[qi][e] * kf[e];
                #pragma unroll
                for (int off = 16; off; off >>= 1) d += __shfl_xor_sync(0xffffffffu, d, off);
                if (lane == j) sraw[qi] = d;
            }
        }

        float p[4];
        #pragma unroll
        for (int qi = 0; qi < 4; qi++) {
            int q = q0 + qi;
            float sc = softcap_tanh(sraw[qi] * SCALE_);
            bool valid = keyvalid;
            if (is_self) valid = valid && (jg <= q) && (q - jg < WINDOW_) && (segj == myseg[qi]);
            if (!valid) sc = -1e30f;
            float tm = sc;
            #pragma unroll
            for (int off = 16; off; off >>= 1) tm = fmaxf(tm, __shfl_xor_sync(0xffffffffu, tm, off));
            float mnew = fmaxf(m[qi], tm);
            float corr = __expf(m[qi] - mnew);
            m[qi] = mnew;
            float pp = __expf(sc - mnew);
            p[qi] = pp;
            float ps = pp;
            #pragma unroll
            for (int off = 16; off; off >>= 1) ps += __shfl_xor_sync(0xffffffffu, ps, off);
            l[qi] = l[qi] * corr + ps;
            #pragma unroll
            for (int e = 0; e < 8; e++) o[qi][e] *= corr;
        }

        #pragma unroll
        for (int j = 0; j < 32; j++) {
            float pj0 = __shfl_sync(0xffffffffu, p[0], j);
            float pj1 = __shfl_sync(0xffffffffu, p[1], j);
            float pj2 = __shfl_sync(0xffffffffu, p[2], j);
            float pj3 = __shfl_sync(0xffffffffu, p[3], j);
            #pragma unroll
            for (int e = 0; e < 8; e++) {
                float v = Vs[j][e*32 + lane];
                o[0][e] += pj0 * v;
                o[1][e] += pj1 * v;
                o[2][e] += pj2 * v;
                o[3][e] += pj3 * v;
            }
        }
    }

    #pragma unroll
    for (int qi = 0; qi < 4; qi++) {
        float inv = 1.0f / l[qi];
        float* op = g_attn + ((size_t)((b*S_ + q0 + qi)*H_ + h)) * HD_;
        #pragma unroll
        for (int e = 0; e < 8; e++) op[e*32 + lane] = o[qi][e] * inv;
    }
}

// ---------------- launch ----------------------------------------------------
extern "C" void kernel_launch(void* const* d_in, const int* in_sizes, int n_in,
                              void* d_out, int out_size)
{
    const float* hs   = (const float*)d_in[0];
    const float* enc  = (const float*)d_in[1];
    const float* cosp = (const float*)d_in[2];
    const float* sinp = (const float*)d_in[3];
    const float* wq   = (const float*)d_in[4];
    const float* wk   = (const float*)d_in[5];
    const float* wv   = (const float*)d_in[6];
    const float* wo   = (const float*)d_in[7];
    const float* qnw  = (const float*)d_in[8];
    const float* knw  = (const float*)d_in[9];
    const int*   dmsk = (const int*)d_in[10];
    const int*   emsk = (const int*)d_in[11];
    const int*   pos  = (const int*)d_in[12];
    float* out = (float*)d_out;

    float *gq, *gks, *gvs, *gkc, *gvc, *gat;
    __nv_bfloat16 *ahi, *alo, *whi, *wlo;
    cudaGetSymbolAddress((void**)&gq,  g_q);
    cudaGetSymbolAddress((void**)&gks, g_kself);
    cudaGetSymbolAddress((void**)&gvs, g_vself);
    cudaGetSymbolAddress((void**)&gkc, g_kcross);
    cudaGetSymbolAddress((void**)&gvc, g_vcross);
    cudaGetSymbolAddress((void**)&gat, g_attn);
    cudaGetSymbolAddress((void**)&ahi, g_act_hi);
    cudaGetSymbolAddress((void**)&alo, g_act_lo);
    cudaGetSymbolAddress((void**)&whi, g_wt_hi);
    cudaGetSymbolAddress((void**)&wlo, g_wt_lo);

    cudaFuncSetAttribute(gemm_hmma_kernel,
                         cudaFuncAttributeMaxDynamicSharedMemorySize, GEMM_SMEM);

    const int MT = B_*S_;     // 2048 token rows
    // decoder activations
    asplit_kernel<<<(MT*D_)/1024, 256>>>(hs, ahi, alo, MT*D_);
    // q = hs @ wq
    wsplit_kernel<<<dim3((H_*HD_)/32, D_/32), 256>>>(wq, whi, wlo, D_, H_*HD_);
    gemm_hmma_kernel<<<dim3((H_*HD_)/128, MT/128), 256, GEMM_SMEM>>>(
        MT, H_*HD_, D_, ahi, alo, whi, wlo, gq);
    // k_self = hs @ wk
    wsplit_kernel<<<dim3((KV_*HD_)/32, D_/32), 256>>>(wk, whi, wlo, D_, KV_*HD_);
    gemm_hmma_kernel<<<dim3((KV_*HD_)/128, MT/128), 256, GEMM_SMEM>>>(
        MT, KV_*HD_, D_, ahi, alo, whi, wlo, gks);
    // v_self = hs @ wv
    wsplit_kernel<<<dim3((KV_*HD_)/32, D_/32), 256>>>(wv, whi, wlo, D_, KV_*HD_);
    gemm_hmma_kernel<<<dim3((KV_*HD_)/128, MT/128), 256, GEMM_SMEM>>>(
        MT, KV_*HD_, D_, ahi, alo, whi, wlo, gvs);
    // encoder activations (wv still resident in wt buffers)
    asplit_kernel<<<(B_*E_*D_)/1024, 256>>>(enc, ahi, alo, B_*E_*D_);
    gemm_hmma_kernel<<<dim3((KV_*HD_)/128, (B_*E_)/128), 256, GEMM_SMEM>>>(
        B_*E_, KV_*HD_, D_, ahi, alo, whi, wlo, gvc);
    // k_cross = enc @ wk
    wsplit_kernel<<<dim3((KV_*HD_)/32, D_/32), 256>>>(wk, whi, wlo, D_, KV_*HD_);
    gemm_hmma_kernel<<<dim3((KV_*HD_)/128, (B_*E_)/128), 256, GEMM_SMEM>>>(
        B_*E_, KV_*HD_, D_, ahi, alo, whi, wlo, gkc);

    // segments, norms, rope
    seg_kernel<<<B_, 1024>>>(pos);
    norm_rope_kernel<<<B_*S_*H_,  256>>>(gq,  qnw, cosp, sinp, H_,  1);
    norm_rope_kernel<<<B_*S_*KV_, 256>>>(gks, knw, cosp, sinp, KV_, 1);
    norm_rope_kernel<<<B_*E_*KV_, 256>>>(gkc, knw, cosp, sinp, KV_, 0);

    // attention
    int smem_bytes = 32 * HD_ * 2 * (int)sizeof(float);
    cudaFuncSetAttribute(attn_kernel, cudaFuncAttributeMaxDynamicSharedMemorySize, smem_bytes);
    attn_kernel<<<dim3(S_/32, H_, B_), 256, smem_bytes>>>(dmsk, emsk);

    // output projection: out = attn @ wo
    asplit_kernel<<<(MT*(H_*HD_))/1024, 256>>>(gat, ahi, alo, MT*H_*HD_);
    wsplit_kernel<<<dim3(D_/32, (H_*HD_)/32), 256>>>(wo, whi, wlo, H_*HD_, D_);
    gemm_hmma_kernel<<<dim3(D_/128, MT/128), 256, GEMM_SMEM>>>(
        MT, D_, H_*HD_, ahi, alo, whi, wlo, out);
}